// round 7
// baseline (speedup 1.0000x reference)
#include <cuda_runtime.h>

// Sub_MGU: block-diagonal MGU recurrence. B=64, T=2048, S=32, H=16.
//   f = sigmoid(x*Wif + b_if + Whf·h + b_hf)
//   n = tanh(x*Win + b_in + f*(Whn·h + b_hn))
//   h' = f*n + (1-f)*h
//
// R6: TWO independent chain-pairs per warp (same subunit -> shared weights),
// interleaved in one instruction stream so each body's FMA work fills the
// other's LDS/MUFU latency shadows. 512 warps -> 128 blocks -> 1 block/SM,
// 1 warp/SMSP: no scheduler interference (R2-R5 showed 2 warps/SMSP don't
// hide each other on this lockstep cadence).
// Per chain: 16 lanes, lane j owns row j of both HxH matrices (f32x2-packed).
// h broadcast via smem + __syncwarp (STS drain, proven in R5). Matvec:
// fma.rn.f32x2, 2 accumulators/gate. f-gate: MUFU tanh.approx (half-angle);
// n-gate: deg-7 odd Taylor. Update: h' = fma(f,n,g), g = fma(-f,h,h) computed
// in parallel with the poly.

#define SUB   32
#define HID   16
#define TSTEP 2048
#define SH    (SUB * HID)

typedef unsigned long long u64;

__device__ __forceinline__ u64 pack2(float lo, float hi) {
    u64 r;
    asm("mov.b64 %0, {%1, %2};" : "=l"(r) : "f"(lo), "f"(hi));
    return r;
}
__device__ __forceinline__ void unpack2(u64 v, float& lo, float& hi) {
    asm("mov.b64 {%0, %1}, %2;" : "=f"(lo), "=f"(hi) : "l"(v));
}
__device__ __forceinline__ void fma2(u64& d, u64 a, u64 b) {
    asm("fma.rn.f32x2 %0, %1, %2, %0;" : "+l"(d) : "l"(a), "l"(b));
}
__device__ __forceinline__ u64 add2(u64 a, u64 b) {
    u64 d;
    asm("add.rn.f32x2 %0, %1, %2;" : "=l"(d) : "l"(a), "l"(b));
    return d;
}
__device__ __forceinline__ float tanh_mufu(float v) {
    float r;
    asm("tanh.approx.f32 %0, %1;" : "=f"(r) : "f"(v));
    return r;
}

__global__ __launch_bounds__(128, 1)
void mgu_kernel(const float* __restrict__ x,
                const float* __restrict__ Wif,
                const float* __restrict__ Win,
                const float* __restrict__ Whf,
                const float* __restrict__ Whn,
                const float* __restrict__ bhi,
                const float* __restrict__ bhh,
                float* __restrict__ out)
{
    const int tid  = threadIdx.x;
    const int lane = tid & 31;
    const int j    = lane & 15;          // hidden index within chain
    const int half = lane >> 4;          // chain within a pair
    const int wl   = tid >> 5;           // warp in block
    const int w    = blockIdx.x * 4 + wl;      // 0..511
    const int s    = w & (SUB - 1);      // subunit (weights shared by warp)
    const int bp   = w >> 5;             // 0..15
    const int bA   = 4 * bp + half;      // chain-pair A batches
    const int bB   = bA + 2;             // chain-pair B batches

    __shared__ __align__(16) float hbuf[4][2][32];
    float* hslotA = &hbuf[wl][0][lane];
    float* hslotB = &hbuf[wl][1][lane];
    const double2* hvecA = reinterpret_cast<const double2*>(&hbuf[wl][0][lane & 16]);
    const double2* hvecB = reinterpret_cast<const double2*>(&hbuf[wl][1][lane & 16]);

    // Shared per-lane weights: row j of both matrices, packed (even k, odd k).
    // Forget-gate side pre-scaled by 0.5 (half-angle sigmoid via tanh).
    u64 w2f[8], w2n[8];
#pragma unroll
    for (int m = 0; m < 8; m++) {
        const int base = (s * HID + j) * HID + 2 * m;
        w2f[m] = pack2(0.5f * Whf[base], 0.5f * Whf[base + 1]);
        w2n[m] = pack2(Whn[base], Whn[base + 1]);
    }
    const float wif_h = 0.5f * Wif[s * HID + j];
    const float win   = Win[s * HID + j];
    const float bf0_h = 0.5f * (bhi[s * HID + j] + bhh[s * HID + j]);
    const float b_in  = bhi[SH + s * HID + j];
    const float b_hn  = bhh[SH + s * HID + j];

    const float* xbaseA = x + (size_t)bA * TSTEP * SUB + s;
    const float* xbaseB = x + (size_t)bB * TSTEP * SUB + s;
    float* obaseA = out + (size_t)bA * TSTEP * SH + s * HID + j;
    float* obaseB = out + (size_t)bB * TSTEP * SH + s * HID + j;

    float hA = 0.0f, hB = 0.0f;
    // x prefetch: lane j holds x for step t0+j (16 steps per buffer)
    float xcurA  = xbaseA[(size_t)j * SUB];
    float xnextA = xbaseA[(size_t)(16 + j) * SUB];
    float xcurB  = xbaseB[(size_t)j * SUB];
    float xnextB = xbaseB[(size_t)(16 + j) * SUB];

    for (int t0 = 0; t0 < TSTEP; t0 += 16) {
#pragma unroll
        for (int i = 0; i < 16; i++) {
            const float xiA = __shfl_sync(0xffffffffu, xcurA, i, 16);
            const float xiB = __shfl_sync(0xffffffffu, xcurB, i, 16);
            const float anxA = fmaf(xiA, win, b_in);
            const float anxB = fmaf(xiB, win, b_in);
            const float afxA = fmaf(xiA, wif_h, bf0_h);
            const float afxB = fmaf(xiB, wif_h, bf0_h);

            // broadcast both h vectors; one syncwarp drains both STS
            *hslotA = hA;
            *hslotB = hB;
            __syncwarp();
            const double2 dA0 = hvecA[0], dA1 = hvecA[1], dA2 = hvecA[2], dA3 = hvecA[3];
            const double2 dB0 = hvecB[0], dB1 = hvecB[1], dB2 = hvecB[2], dB3 = hvecB[3];
            const u64 pA0 = __double_as_longlong(dA0.x), pA1 = __double_as_longlong(dA0.y);
            const u64 pA2 = __double_as_longlong(dA1.x), pA3 = __double_as_longlong(dA1.y);
            const u64 pA4 = __double_as_longlong(dA2.x), pA5 = __double_as_longlong(dA2.y);
            const u64 pA6 = __double_as_longlong(dA3.x), pA7 = __double_as_longlong(dA3.y);
            const u64 pB0 = __double_as_longlong(dB0.x), pB1 = __double_as_longlong(dB0.y);
            const u64 pB2 = __double_as_longlong(dB1.x), pB3 = __double_as_longlong(dB1.y);
            const u64 pB4 = __double_as_longlong(dB2.x), pB5 = __double_as_longlong(dB2.y);
            const u64 pB6 = __double_as_longlong(dB3.x), pB7 = __double_as_longlong(dB3.y);

            // ---- matvecs (2 accumulators per gate-dot) ----
            u64 aFA0 = pack2(afxA, 0.0f), aFA1 = 0ull;
            u64 aNA0 = pack2(b_hn, 0.0f), aNA1 = 0ull;
            u64 aFB0 = pack2(afxB, 0.0f), aFB1 = 0ull;
            u64 aNB0 = pack2(b_hn, 0.0f), aNB1 = 0ull;
            fma2(aFA0, w2f[0], pA0); fma2(aFA1, w2f[1], pA1);
            fma2(aNA0, w2n[0], pA0); fma2(aNA1, w2n[1], pA1);
            fma2(aFB0, w2f[0], pB0); fma2(aFB1, w2f[1], pB1);
            fma2(aNB0, w2n[0], pB0); fma2(aNB1, w2n[1], pB1);
            fma2(aFA0, w2f[2], pA2); fma2(aFA1, w2f[3], pA3);
            fma2(aNA0, w2n[2], pA2); fma2(aNA1, w2n[3], pA3);
            fma2(aFB0, w2f[2], pB2); fma2(aFB1, w2f[3], pB3);
            fma2(aNB0, w2n[2], pB2); fma2(aNB1, w2n[3], pB3);
            fma2(aFA0, w2f[4], pA4); fma2(aFA1, w2f[5], pA5);
            fma2(aNA0, w2n[4], pA4); fma2(aNA1, w2n[5], pA5);
            fma2(aFB0, w2f[4], pB4); fma2(aFB1, w2f[5], pB5);
            fma2(aNB0, w2n[4], pB4); fma2(aNB1, w2n[5], pB5);
            fma2(aFA0, w2f[6], pA6); fma2(aFA1, w2f[7], pA7);
            fma2(aNA0, w2n[6], pA6); fma2(aNA1, w2n[7], pA7);
            fma2(aFB0, w2f[6], pB6); fma2(aFB1, w2f[7], pB7);
            fma2(aNB0, w2n[6], pB6); fma2(aNB1, w2n[7], pB7);

            float fla, fha, nla, nha, flb, fhb, nlb, nhb;
            unpack2(add2(aFA0, aFA1), fla, fha);
            unpack2(add2(aNA0, aNA1), nla, nha);
            unpack2(add2(aFB0, aFB1), flb, fhb);
            unpack2(add2(aNB0, aNB1), nlb, nhb);
            const float aA  = fla + fha;   // (i_f + h_f)/2
            const float hnA = nla + nha;   // h_n (incl. bias)
            const float aB  = flb + fhb;
            const float hnB = nlb + nhb;

            // f = 0.5 + 0.5*tanh(a)
            const float fA = fmaf(tanh_mufu(aA), 0.5f, 0.5f);
            const float fB = fmaf(tanh_mufu(aB), 0.5f, 0.5f);
            // g = (1-f)*h, computed in parallel with the poly
            const float gA = fmaf(-fA, hA, hA);
            const float gB = fmaf(-fB, hB, hB);

            // n = tanh(anx + f*hn), deg-7 odd Taylor
            const float argA = fmaf(fA, hnA, anxA);
            const float argB = fmaf(fB, hnB, anxB);
            const float yA = argA * argA;
            const float yB = argB * argB;
            float pA = fmaf(yA, -0.053968254f, 0.13333333f);
            float pB = fmaf(yB, -0.053968254f, 0.13333333f);
            pA = fmaf(yA, pA, -0.33333333f);
            pB = fmaf(yB, pB, -0.33333333f);
            pA = fmaf(yA, pA, 1.0f);
            pB = fmaf(yB, pB, 1.0f);
            const float nA = argA * pA;
            const float nB = argB * pB;

            hA = fmaf(fA, nA, gA);
            hB = fmaf(fB, nB, gB);

            obaseA[(size_t)(t0 + i) * SH] = hA;
            obaseB[(size_t)(t0 + i) * SH] = hB;
        }
        xcurA = xnextA;
        xcurB = xnextB;
        int tn = t0 + 32 + j;
        if (tn >= TSTEP) tn = TSTEP - 1;   // predicated, no divergence
        xnextA = xbaseA[(size_t)tn * SUB];
        xnextB = xbaseB[(size_t)tn * SUB];
    }
}

extern "C" void kernel_launch(void* const* d_in, const int* in_sizes, int n_in,
                              void* d_out, int out_size)
{
    const float* x   = (const float*)d_in[0];
    const float* Wif = (const float*)d_in[1];
    const float* Win = (const float*)d_in[2];
    const float* Whf = (const float*)d_in[3];
    const float* Whn = (const float*)d_in[4];
    const float* bhi = (const float*)d_in[5];
    const float* bhh = (const float*)d_in[6];

    // 512 warps = 32 subunits * 16 batch-quads; 4 warps/block -> 128 blocks
    // -> 1 block/SM, 1 warp/SMSP.
    mgu_kernel<<<128, 128>>>(x, Wif, Win, Whf, Whn, bhi, bhh, (float*)d_out);
}